// round 1
// baseline (speedup 1.0000x reference)
#include <cuda_runtime.h>

// Problem shape (fixed by the dataset): x[B=64, C=256, H=56, W=56] fp32
#define C_    256
#define B_    64
#define HW_   3136
#define HW4_  784        // HW/4 (float4 units per image plane)
#define NPC_  200704     // B*HW elements per channel
#define EPS_  1e-5f

// Scratch: partial sums per (channel, batch), plus fused scale/bias.
__device__ float g_psum[C_ * B_];
__device__ float g_psq [C_ * B_];
__device__ float g_scale[C_];
__device__ float g_bias [C_];

// ---------------------------------------------------------------------------
// Pass 1: per-(batch, channel) partial sum / sum-of-squares.
// One block = one 56x56 image plane = 784 float4 loads. 256 threads.
// ---------------------------------------------------------------------------
__global__ __launch_bounds__(256) void reduce_k(const float4* __restrict__ x) {
    const int b = blockIdx.x;
    const int c = blockIdx.y;
    const float4* p = x + ((size_t)b * C_ + c) * HW4_;

    float s = 0.f, sq = 0.f;
    #pragma unroll 4
    for (int i = threadIdx.x; i < HW4_; i += 256) {
        float4 v = p[i];
        s  += (v.x + v.y) + (v.z + v.w);
        sq += v.x * v.x + v.y * v.y + v.z * v.z + v.w * v.w;
    }

    // warp reduce
    #pragma unroll
    for (int o = 16; o > 0; o >>= 1) {
        s  += __shfl_xor_sync(0xffffffffu, s,  o);
        sq += __shfl_xor_sync(0xffffffffu, sq, o);
    }

    __shared__ float ss[8], ssq[8];
    const int w = threadIdx.x >> 5, l = threadIdx.x & 31;
    if (l == 0) { ss[w] = s; ssq[w] = sq; }
    __syncthreads();

    if (threadIdx.x == 0) {
        float ts = 0.f, tq = 0.f;
        #pragma unroll
        for (int i = 0; i < 8; i++) { ts += ss[i]; tq += ssq[i]; }
        g_psum[c * B_ + b] = ts;
        g_psq [c * B_ + b] = tq;
    }
}

// ---------------------------------------------------------------------------
// Pass 1b: fold 64 batch-partials per channel, produce fused scale/bias.
// One block, 256 threads (= one thread per channel).
// ---------------------------------------------------------------------------
__global__ __launch_bounds__(256) void finalize_k(const float* __restrict__ gamma,
                                                  const float* __restrict__ beta) {
    const int c = threadIdx.x;
    float s = 0.f, sq = 0.f;
    #pragma unroll
    for (int b = 0; b < B_; b++) {
        s  += g_psum[c * B_ + b];
        sq += g_psq [c * B_ + b];
    }
    const float inv_n = 1.f / (float)NPC_;
    const float mean  = s * inv_n;
    const float var   = sq * inv_n - mean * mean;   // biased variance
    const float sc    = gamma[c] * rsqrtf(var + EPS_);
    g_scale[c] = sc;
    g_bias[c]  = beta[c] - mean * sc;
}

// ---------------------------------------------------------------------------
// Pass 2: out = x * scale[c] + bias[c].
// One block = one image plane, 784 threads, one float4 per thread.
// scale/bias are uniform per block (blockIdx.y = channel).
// ---------------------------------------------------------------------------
__global__ __launch_bounds__(784) void norm_k(const float4* __restrict__ x,
                                              float4* __restrict__ out) {
    const int b = blockIdx.x;
    const int c = blockIdx.y;
    const float sc = g_scale[c];
    const float bi = g_bias[c];

    const size_t off = ((size_t)b * C_ + c) * HW4_ + threadIdx.x;
    float4 v = x[off];
    v.x = fmaf(v.x, sc, bi);
    v.y = fmaf(v.y, sc, bi);
    v.z = fmaf(v.z, sc, bi);
    v.w = fmaf(v.w, sc, bi);
    out[off] = v;
}

// ---------------------------------------------------------------------------
extern "C" void kernel_launch(void* const* d_in, const int* in_sizes, int n_in,
                              void* d_out, int out_size) {
    const float* x     = (const float*)d_in[0];
    const float* gamma = (const float*)d_in[1];
    const float* beta  = (const float*)d_in[2];
    float* out = (float*)d_out;

    dim3 grid(B_, C_);
    reduce_k<<<grid, 256>>>((const float4*)x);
    finalize_k<<<1, C_>>>(gamma, beta);
    norm_k<<<grid, 784>>>((const float4*)x, (float4*)out);
}

// round 2
// speedup vs baseline: 1.2084x; 1.2084x over previous
#include <cuda_runtime.h>

// Problem shape (fixed): x[B=64, C=256, H=56, W=56] fp32
#define C_    256
#define B_    64
#define HW4_  784        // HW/4 (float4 per image plane); 784 = 3*256 + 16
#define NPC_  200704     // B*HW elements per channel
#define EPS_  1e-5f

__device__ float g_psum[C_ * B_];
__device__ float g_psq [C_ * B_];
__device__ float g_scale[C_];
__device__ float g_bias [C_];

// ---------------------------------------------------------------------------
// Pass 1: per-(batch, channel) partials. 256 threads, batched MLP-4 loads.
// ---------------------------------------------------------------------------
__global__ __launch_bounds__(256) void reduce_k(const float4* __restrict__ x) {
    const int b = blockIdx.x;
    const int c = blockIdx.y;
    const float4* p = x + ((size_t)b * C_ + c) * HW4_;
    const int t = threadIdx.x;

    // Batch all loads up front -> 4 outstanding LDG.128 per thread.
    float4 v0 = __ldcs(p + t);
    float4 v1 = __ldcs(p + t + 256);
    float4 v2 = __ldcs(p + t + 512);
    float4 v3 = make_float4(0.f, 0.f, 0.f, 0.f);
    if (t < HW4_ - 768) v3 = __ldcs(p + t + 768);   // t < 16

    float s  = (v0.x + v0.y) + (v0.z + v0.w)
             + (v1.x + v1.y) + (v1.z + v1.w)
             + (v2.x + v2.y) + (v2.z + v2.w)
             + (v3.x + v3.y) + (v3.z + v3.w);
    float sq = v0.x*v0.x + v0.y*v0.y + v0.z*v0.z + v0.w*v0.w
             + v1.x*v1.x + v1.y*v1.y + v1.z*v1.z + v1.w*v1.w
             + v2.x*v2.x + v2.y*v2.y + v2.z*v2.z + v2.w*v2.w
             + v3.x*v3.x + v3.y*v3.y + v3.z*v3.z + v3.w*v3.w;

    #pragma unroll
    for (int o = 16; o > 0; o >>= 1) {
        s  += __shfl_xor_sync(0xffffffffu, s,  o);
        sq += __shfl_xor_sync(0xffffffffu, sq, o);
    }

    __shared__ float ss[8], ssq[8];
    const int w = t >> 5, l = t & 31;
    if (l == 0) { ss[w] = s; ssq[w] = sq; }
    __syncthreads();

    if (t == 0) {
        float ts = 0.f, tq = 0.f;
        #pragma unroll
        for (int i = 0; i < 8; i++) { ts += ss[i]; tq += ssq[i]; }
        g_psum[c * B_ + b] = ts;
        g_psq [c * B_ + b] = tq;
    }
}

// ---------------------------------------------------------------------------
// Fold partials, produce fused scale/bias. One block of 256 threads.
// ---------------------------------------------------------------------------
__global__ __launch_bounds__(256) void finalize_k(const float* __restrict__ gamma,
                                                  const float* __restrict__ beta) {
    const int c = threadIdx.x;
    float s = 0.f, sq = 0.f;
    #pragma unroll
    for (int b = 0; b < B_; b++) {
        s  += g_psum[c * B_ + b];
        sq += g_psq [c * B_ + b];
    }
    const float inv_n = 1.f / (float)NPC_;
    const float mean  = s * inv_n;
    const float var   = sq * inv_n - mean * mean;
    const float sc    = gamma[c] * rsqrtf(var + EPS_);
    g_scale[c] = sc;
    g_bias[c]  = beta[c] - mean * sc;
}

// ---------------------------------------------------------------------------
// Pass 2: out = x*scale + bias. 256 threads, MLP-4 batched loads, streaming st.
// ---------------------------------------------------------------------------
__global__ __launch_bounds__(256) void norm_k(const float4* __restrict__ x,
                                              float4* __restrict__ out) {
    const int b = blockIdx.x;
    const int c = blockIdx.y;
    const float sc = g_scale[c];
    const float bi = g_bias[c];

    const size_t base = ((size_t)b * C_ + c) * HW4_;
    const int t = threadIdx.x;
    const float4* p = x + base;
    float4* q = out + base;

    float4 v0 = __ldcs(p + t);
    float4 v1 = __ldcs(p + t + 256);
    float4 v2 = __ldcs(p + t + 512);
    float4 v3;
    const bool tail = (t < HW4_ - 768);
    if (tail) v3 = __ldcs(p + t + 768);

    v0.x = fmaf(v0.x, sc, bi); v0.y = fmaf(v0.y, sc, bi);
    v0.z = fmaf(v0.z, sc, bi); v0.w = fmaf(v0.w, sc, bi);
    v1.x = fmaf(v1.x, sc, bi); v1.y = fmaf(v1.y, sc, bi);
    v1.z = fmaf(v1.z, sc, bi); v1.w = fmaf(v1.w, sc, bi);
    v2.x = fmaf(v2.x, sc, bi); v2.y = fmaf(v2.y, sc, bi);
    v2.z = fmaf(v2.z, sc, bi); v2.w = fmaf(v2.w, sc, bi);

    __stcs(q + t,       v0);
    __stcs(q + t + 256, v1);
    __stcs(q + t + 512, v2);
    if (tail) {
        v3.x = fmaf(v3.x, sc, bi); v3.y = fmaf(v3.y, sc, bi);
        v3.z = fmaf(v3.z, sc, bi); v3.w = fmaf(v3.w, sc, bi);
        __stcs(q + t + 768, v3);
    }
}

// ---------------------------------------------------------------------------
extern "C" void kernel_launch(void* const* d_in, const int* in_sizes, int n_in,
                              void* d_out, int out_size) {
    const float* x     = (const float*)d_in[0];
    const float* gamma = (const float*)d_in[1];
    const float* beta  = (const float*)d_in[2];
    float* out = (float*)d_out;

    dim3 grid(B_, C_);
    reduce_k<<<grid, 256>>>((const float4*)x);
    finalize_k<<<1, C_>>>(gamma, beta);
    norm_k<<<grid, 256>>>((const float4*)x, (float4*)out);
}

// round 5
// speedup vs baseline: 1.2390x; 1.0253x over previous
#include <cuda_runtime.h>

// Problem shape (fixed): x[B=64, C=256, H=56, W=56] fp32
#define C_    256
#define B_    64
#define HW4_  784        // HW/4 (float4 per plane)
#define NPC_  200704     // B*HW elements per channel
#define EPS_  1e-5f
#define N4_   12845056   // total float4 = B*C*HW4

__device__ float g_psum[C_ * B_];
__device__ float g_psq [C_ * B_];
__device__ float g_scale[C_];
__device__ float g_bias [C_];

__device__ __forceinline__ float fsum4(const float4 v)  { return (v.x + v.y) + (v.z + v.w); }
__device__ __forceinline__ float fsq4 (const float4 v)  { return v.x*v.x + v.y*v.y + v.z*v.z + v.w*v.w; }

// ---------------------------------------------------------------------------
// Pass 1: two planes (b, 2c) and (b, 2c+1) per block. 1568 float4,
// 256 threads, 6 unconditional + 1 predicated LDG.128 (MLP ~7).
// ---------------------------------------------------------------------------
__global__ __launch_bounds__(256) void reduce_k(const float4* __restrict__ x) {
    const int b  = blockIdx.x;
    const int c2 = blockIdx.y;                  // channel pair index
    const float4* p = x + ((size_t)b * C_ + 2 * c2) * HW4_;
    const int t = threadIdx.x;

    float4 v0 = __ldcs(p + t);
    float4 v1 = __ldcs(p + t + 256);
    float4 v2 = __ldcs(p + t + 512);
    float4 v3 = __ldcs(p + t + 768);            // straddles plane boundary at 784
    float4 v4 = __ldcs(p + t + 1024);
    float4 v5 = __ldcs(p + t + 1280);
    float4 v6 = make_float4(0.f, 0.f, 0.f, 0.f);
    if (t < 32) v6 = __ldcs(p + t + 1536);      // tail of plane 1

    float s0 = fsum4(v0) + fsum4(v1) + fsum4(v2);
    float q0 = fsq4 (v0) + fsq4 (v1) + fsq4 (v2);
    float s1 = fsum4(v4) + fsum4(v5) + fsum4(v6);
    float q1 = fsq4 (v4) + fsq4 (v5) + fsq4 (v6);
    // j=3: idx = t+768; plane0 iff idx < 784 i.e. t < 16
    const float s3 = fsum4(v3), q3 = fsq4(v3);
    if (t < 16) { s0 += s3; q0 += q3; } else { s1 += s3; q1 += q3; }

    #pragma unroll
    for (int o = 16; o > 0; o >>= 1) {
        s0 += __shfl_xor_sync(0xffffffffu, s0, o);
        q0 += __shfl_xor_sync(0xffffffffu, q0, o);
        s1 += __shfl_xor_sync(0xffffffffu, s1, o);
        q1 += __shfl_xor_sync(0xffffffffu, q1, o);
    }

    __shared__ float sh[4][8];
    const int w = t >> 5, l = t & 31;
    if (l == 0) { sh[0][w] = s0; sh[1][w] = q0; sh[2][w] = s1; sh[3][w] = q1; }
    __syncthreads();

    if (t < 2) {   // t=0 -> plane0, t=1 -> plane1
        float ts = 0.f, tq = 0.f;
        #pragma unroll
        for (int i = 0; i < 8; i++) { ts += sh[2 * t][i]; tq += sh[2 * t + 1][i]; }
        const int c = 2 * c2 + t;
        g_psum[c * B_ + b] = ts;
        g_psq [c * B_ + b] = tq;
    }
}

// ---------------------------------------------------------------------------
// Fold partials -> fused scale/bias. One block of 256 threads.
// ---------------------------------------------------------------------------
__global__ __launch_bounds__(256) void finalize_k(const float* __restrict__ gamma,
                                                  const float* __restrict__ beta) {
    const int c = threadIdx.x;
    float s = 0.f, sq = 0.f;
    #pragma unroll
    for (int b = 0; b < B_; b++) {
        s  += g_psum[c * B_ + b];
        sq += g_psq [c * B_ + b];
    }
    const float inv_n = 1.f / (float)NPC_;
    const float mean  = s * inv_n;
    const float var   = sq * inv_n - mean * mean;
    const float sc    = gamma[c] * rsqrtf(var + EPS_);
    g_scale[c] = sc;
    g_bias[c]  = beta[c] - mean * sc;
}

// ---------------------------------------------------------------------------
// Pass 2: flat elementwise, 6272 blocks x 256 threads x 8 float4 (no tail).
// All 8 loads batched up front (MLP 8); channel via idx/784 (magic mul).
// ---------------------------------------------------------------------------
__global__ __launch_bounds__(256) void norm_k(const float4* __restrict__ x,
                                              float4* __restrict__ out) {
    const int base = blockIdx.x * 2048 + threadIdx.x;

    float4 v[8];
    #pragma unroll
    for (int j = 0; j < 8; j++) v[j] = __ldcs(x + base + 256 * j);

    #pragma unroll
    for (int j = 0; j < 8; j++) {
        const int idx = base + 256 * j;
        const int c   = (idx / HW4_) & (C_ - 1);      // plane mod C
        const float sc = g_scale[c];
        const float bi = g_bias[c];
        v[j].x = fmaf(v[j].x, sc, bi);
        v[j].y = fmaf(v[j].y, sc, bi);
        v[j].z = fmaf(v[j].z, sc, bi);
        v[j].w = fmaf(v[j].w, sc, bi);
        __stcs(out + idx, v[j]);
    }
}

// ---------------------------------------------------------------------------
extern "C" void kernel_launch(void* const* d_in, const int* in_sizes, int n_in,
                              void* d_out, int out_size) {
    const float* x     = (const float*)d_in[0];
    const float* gamma = (const float*)d_in[1];
    const float* beta  = (const float*)d_in[2];
    float* out = (float*)d_out;

    dim3 rgrid(B_, C_ / 2);
    reduce_k<<<rgrid, 256>>>((const float4*)x);
    finalize_k<<<1, C_>>>(gamma, beta);
    norm_k<<<N4_ / 2048, 256>>>((const float4*)x, (float4*)out);
}

// round 6
// speedup vs baseline: 1.3216x; 1.0667x over previous
#include <cuda_runtime.h>

// Problem shape (fixed): x[B=64, C=256, H=56, W=56] fp32
#define C_    256
#define B_    64
#define HW4_  784        // HW/4 (float4 per plane)
#define NPC_  200704     // B*HW elements per channel
#define EPS_  1e-5f
#define N4_   12845056   // total float4 = B*C*HW4
#define NBLK_ 6272       // norm blocks: N4 / 2048
// Blocks whose linear start (in float4) is >= this keep their lines in L2
// (evict-normal) so the reversed norm pass can hit them. ~53% tail ≈ 109 MB.
#define RESIDENT_START_ 6000000

__device__ float g_psum[C_ * B_];
__device__ float g_psq [C_ * B_];
__device__ float g_scale[C_];
__device__ float g_bias [C_];

__device__ __forceinline__ float fsum4(const float4 v)  { return (v.x + v.y) + (v.z + v.w); }
__device__ __forceinline__ float fsq4 (const float4 v)  { return v.x*v.x + v.y*v.y + v.z*v.z + v.w*v.w; }

// ---------------------------------------------------------------------------
// Pass 1: two planes (b, 2c) and (b, 2c+1) per block. 1568 float4, 256 thr.
// Grid: (c2 fast, b slow) so block execution order matches linear address
// order -> the LAST-executed blocks cover the address-space tail.
// Front 47%: streaming loads (evict-first). Tail 53%: evict-normal, so the
// tail of x stays L2-resident for the reversed norm pass.
// ---------------------------------------------------------------------------
__global__ __launch_bounds__(256) void reduce_k(const float4* __restrict__ x) {
    const int c2 = blockIdx.x;                  // channel pair index (fast)
    const int b  = blockIdx.y;                  // batch (slow)
    const size_t start4 = ((size_t)b * C_ + 2 * c2) * HW4_;
    const float4* p = x + start4;
    const int t = threadIdx.x;
    const bool keep = (start4 >= (size_t)RESIDENT_START_);

    float4 v0, v1, v2, v3, v4, v5, v6;
    v6 = make_float4(0.f, 0.f, 0.f, 0.f);
    if (keep) {
        v0 = p[t];        v1 = p[t + 256];  v2 = p[t + 512];
        v3 = p[t + 768];  v4 = p[t + 1024]; v5 = p[t + 1280];
        if (t < 32) v6 = p[t + 1536];
    } else {
        v0 = __ldcs(p + t);        v1 = __ldcs(p + t + 256);
        v2 = __ldcs(p + t + 512);  v3 = __ldcs(p + t + 768);
        v4 = __ldcs(p + t + 1024); v5 = __ldcs(p + t + 1280);
        if (t < 32) v6 = __ldcs(p + t + 1536);
    }

    float s0 = fsum4(v0) + fsum4(v1) + fsum4(v2);
    float q0 = fsq4 (v0) + fsq4 (v1) + fsq4 (v2);
    float s1 = fsum4(v4) + fsum4(v5) + fsum4(v6);
    float q1 = fsq4 (v4) + fsq4 (v5) + fsq4 (v6);
    // j=3 straddles the plane boundary at 784: plane0 iff t < 16
    const float s3 = fsum4(v3), q3 = fsq4(v3);
    if (t < 16) { s0 += s3; q0 += q3; } else { s1 += s3; q1 += q3; }

    #pragma unroll
    for (int o = 16; o > 0; o >>= 1) {
        s0 += __shfl_xor_sync(0xffffffffu, s0, o);
        q0 += __shfl_xor_sync(0xffffffffu, q0, o);
        s1 += __shfl_xor_sync(0xffffffffu, s1, o);
        q1 += __shfl_xor_sync(0xffffffffu, q1, o);
    }

    __shared__ float sh[4][8];
    const int w = t >> 5, l = t & 31;
    if (l == 0) { sh[0][w] = s0; sh[1][w] = q0; sh[2][w] = s1; sh[3][w] = q1; }
    __syncthreads();

    if (t < 2) {   // t=0 -> plane0, t=1 -> plane1
        float ts = 0.f, tq = 0.f;
        #pragma unroll
        for (int i = 0; i < 8; i++) { ts += sh[2 * t][i]; tq += sh[2 * t + 1][i]; }
        const int c = 2 * c2 + t;
        g_psum[c * B_ + b] = ts;
        g_psq [c * B_ + b] = tq;
    }
}

// ---------------------------------------------------------------------------
// Fold partials -> fused scale/bias. One block of 256 threads.
// ---------------------------------------------------------------------------
__global__ __launch_bounds__(256) void finalize_k(const float* __restrict__ gamma,
                                                  const float* __restrict__ beta) {
    const int c = threadIdx.x;
    float s = 0.f, sq = 0.f;
    #pragma unroll
    for (int b = 0; b < B_; b++) {
        s  += g_psum[c * B_ + b];
        sq += g_psq [c * B_ + b];
    }
    const float inv_n = 1.f / (float)NPC_;
    const float mean  = s * inv_n;
    const float var   = sq * inv_n - mean * mean;
    const float sc    = gamma[c] * rsqrtf(var + EPS_);
    g_scale[c] = sc;
    g_bias[c]  = beta[c] - mean * sc;
}

// ---------------------------------------------------------------------------
// Pass 2: flat elementwise, REVERSED block order so the first-executed blocks
// consume the L2-resident tail left by reduce_k before anything evicts it.
// 6272 blocks x 256 threads x 8 float4, no tail predication.
// ---------------------------------------------------------------------------
__global__ __launch_bounds__(256) void norm_k(const float4* __restrict__ x,
                                              float4* __restrict__ out) {
    const int base = (NBLK_ - 1 - (int)blockIdx.x) * 2048 + (int)threadIdx.x;

    float4 v[8];
    #pragma unroll
    for (int j = 0; j < 8; j++) v[j] = __ldcs(x + base + 256 * j);

    #pragma unroll
    for (int j = 0; j < 8; j++) {
        const int idx = base + 256 * j;
        const int c   = (idx / HW4_) & (C_ - 1);      // plane mod C
        const float sc = g_scale[c];
        const float bi = g_bias[c];
        v[j].x = fmaf(v[j].x, sc, bi);
        v[j].y = fmaf(v[j].y, sc, bi);
        v[j].z = fmaf(v[j].z, sc, bi);
        v[j].w = fmaf(v[j].w, sc, bi);
        __stcs(out + idx, v[j]);
    }
}

// ---------------------------------------------------------------------------
extern "C" void kernel_launch(void* const* d_in, const int* in_sizes, int n_in,
                              void* d_out, int out_size) {
    const float* x     = (const float*)d_in[0];
    const float* gamma = (const float*)d_in[1];
    const float* beta  = (const float*)d_in[2];
    float* out = (float*)d_out;

    dim3 rgrid(C_ / 2, B_);     // c2 fast, b slow -> execution ~ address order
    reduce_k<<<rgrid, 256>>>((const float4*)x);
    finalize_k<<<1, C_>>>(gamma, beta);
    norm_k<<<NBLK_, 256>>>((const float4*)x, (float4*)out);
}